// round 1
// baseline (speedup 1.0000x reference)
#include <cuda_runtime.h>
#include <cstdint>

#define NN 100000
#define NH 20000
#define NE 800000

// ---------------- scratch (static device arrays; no runtime alloc) ----------
// layout: ef [NH*128] | no [NN*128] | D [2*NN] | B [2*NH]
#define EF_OFF 0
#define NO_OFF (NH*128)
#define D_OFF  (NH*128 + NN*128)
#define B_OFF  (NH*128 + NN*128 + 2*NN)
#define ZTOT   (NH*128 + NN*128 + 2*NN + 2*NH)   // 15,600,000 floats (zeroed each call)

__device__ float g_scratch[ZTOT];
__device__ float g_xl[(size_t)NN*128];   // x @ [W_conv0|W_conv1]
__device__ float g_h[(size_t)NN*64];     // relu(mix)
__device__ float g_Bcomb[128*256];       // combined GRU weight matrix
__device__ float g_bias[256];            // combined GRU bias

__device__ __forceinline__ void red_add_f4(float* addr, float4 v) {
    asm volatile("red.global.add.v4.f32 [%0], {%1,%2,%3,%4};"
                 :: "l"(addr), "f"(v.x), "f"(v.y), "f"(v.z), "f"(v.w) : "memory");
}

// ---------------- zero scratch ----------------------------------------------
__global__ void k_zero() {
    int i = blockIdx.x * blockDim.x + threadIdx.x;
    const int n4 = ZTOT / 4;
    float4 z = make_float4(0.f, 0.f, 0.f, 0.f);
    for (; i < n4; i += gridDim.x * blockDim.x)
        reinterpret_cast<float4*>(g_scratch)[i] = z;
}

// ---------------- build combined GRU weights --------------------------------
// output cols: [0,64)=r-sum  [64,128)=z-sum  [128,192)=gi_n  [192,256)=gh_n
// input rows:  k<64 -> h, k>=64 -> h_prev
__global__ void k_prep(const float* __restrict__ Wih, const float* __restrict__ Whh,
                       const float* __restrict__ bih, const float* __restrict__ bhh) {
    int idx = blockIdx.x * blockDim.x + threadIdx.x;
    if (idx < 128 * 256) {
        int k = idx >> 8, c = idx & 255;
        int seg = c >> 6, j = c & 63;
        float v = 0.f;
        if (k < 64) {
            if (seg == 0)      v = Wih[k*192 + j];
            else if (seg == 1) v = Wih[k*192 + 64 + j];
            else if (seg == 2) v = Wih[k*192 + 128 + j];
        } else {
            int kk = k - 64;
            if (seg == 0)      v = Whh[kk*192 + j];
            else if (seg == 1) v = Whh[kk*192 + 64 + j];
            else if (seg == 3) v = Whh[kk*192 + 128 + j];
        }
        g_Bcomb[idx] = v;
    }
    if (idx < 256) {
        int seg = idx >> 6, j = idx & 63;
        float b;
        if (seg == 0)      b = bih[j] + bhh[j];
        else if (seg == 1) b = bih[64 + j] + bhh[64 + j];
        else if (seg == 2) b = bih[128 + j];
        else               b = bhh[128 + j];
        g_bias[idx] = b;
    }
}

// ---------------- xl = x @ [W_conv0 | W_conv1]  ([NN,64]@[64,128]) ----------
__global__ void k_gemm_xl(const float* __restrict__ x, const float* __restrict__ Wc) {
    __shared__ float Xs[64][64];    // node-major
    __shared__ float Ws[64][128];   // k-major
    int n0 = blockIdx.x * 64;
    int tid = threadIdx.x;
    for (int i = tid; i < 64 * 64; i += 256) {
        int nl = i >> 6, k = i & 63;
        int n = n0 + nl;
        Xs[nl][k] = (n < NN) ? x[n * 64 + k] : 0.f;
    }
    for (int i = tid; i < 64 * 128; i += 256) {
        int k = i >> 7, c = i & 127;
        Ws[k][c] = Wc[(c >> 6) * 4096 + k * 64 + (c & 63)];
    }
    __syncthreads();
    int rt = tid >> 5, ct = tid & 31;   // 8 row-groups x 8 nodes; 32 col-groups x 4 cols
    float acc[8][4] = {};
#pragma unroll 8
    for (int k = 0; k < 64; k++) {
        float4 b = *reinterpret_cast<float4*>(&Ws[k][ct * 4]);
#pragma unroll
        for (int i = 0; i < 8; i++) {
            float a = Xs[rt * 8 + i][k];
            acc[i][0] += a * b.x; acc[i][1] += a * b.y;
            acc[i][2] += a * b.z; acc[i][3] += a * b.w;
        }
    }
#pragma unroll
    for (int i = 0; i < 8; i++) {
        int n = n0 + rt * 8 + i;
        if (n < NN)
            *reinterpret_cast<float4*>(&g_xl[(size_t)n * 128 + ct * 4]) =
                *reinterpret_cast<float4*>(acc[i]);
    }
}

// ---------------- scatter phase A: ef += xl[node], degrees ------------------
__global__ void k_scatterA(const int* __restrict__ ni, const int* __restrict__ hi,
                           const int* __restrict__ ea) {
    int tid = blockIdx.x * 256 + threadIdx.x;
    int e = tid >> 4, lane = tid & 15;
    if (e >= NE) return;
    int n = ni[e], h = hi[e], t = ea[e];
    float4 v = *reinterpret_cast<const float4*>(&g_xl[(size_t)n * 128 + t * 64 + lane * 4]);
    red_add_f4(&g_scratch[EF_OFF + (size_t)h * 128 + t * 64 + lane * 4], v);
    if (lane == 0) {
        atomicAdd(&g_scratch[D_OFF + t * NN + n], 1.0f);
        atomicAdd(&g_scratch[B_OFF + t * NH + h], 1.0f);
    }
}

// ---------------- ef *= Binv -------------------------------------------------
__global__ void k_scale_ef() {
    int i = blockIdx.x * 256 + threadIdx.x;   // one float4 each
    if (i >= NH * 32) return;
    int h = i >> 5, c4 = i & 31;
    int t = c4 >> 4;
    float b = g_scratch[B_OFF + t * NH + h];
    float s = (b > 0.f) ? 1.f / b : 0.f;
    float4* p = reinterpret_cast<float4*>(&g_scratch[EF_OFF + (size_t)h * 128 + c4 * 4]);
    float4 v = *p;
    v.x *= s; v.y *= s; v.z *= s; v.w *= s;
    *p = v;
}

// ---------------- scatter phase B: no += ef[hedge] ---------------------------
__global__ void k_scatterB(const int* __restrict__ ni, const int* __restrict__ hi,
                           const int* __restrict__ ea) {
    int tid = blockIdx.x * 256 + threadIdx.x;
    int e = tid >> 4, lane = tid & 15;
    if (e >= NE) return;
    int n = ni[e], h = hi[e], t = ea[e];
    float4 v = *reinterpret_cast<const float4*>(
        &g_scratch[EF_OFF + (size_t)h * 128 + t * 64 + lane * 4]);
    red_add_f4(&g_scratch[NO_OFF + (size_t)n * 128 + t * 64 + lane * 4], v);
}

// ---------------- h = relu((no*Dinv + b_conv) @ W_mix + b_mix) --------------
__global__ void k_mix(const float* __restrict__ bconv, const float* __restrict__ Wmix,
                      const float* __restrict__ bmix) {
    __shared__ float Xs[64][64];
    __shared__ float Ws[64][64];
    int n0 = blockIdx.x * 64;
    int tid = threadIdx.x;
    int rt = tid >> 4, ct = tid & 15;   // 16 row-groups x 4 nodes; 16 col-groups x 4 cols
    float acc[4][4] = {};
    for (int kc = 0; kc < 2; kc++) {
        __syncthreads();
        for (int i = tid; i < 4096; i += 256) {
            int nl = i >> 6, kk = i & 63;
            int n = n0 + nl;
            float v = 0.f;
            if (n < NN) {
                float d = g_scratch[D_OFF + kc * NN + n];
                float dinv = (d > 0.f) ? 1.f / d : 0.f;
                v = g_scratch[NO_OFF + (size_t)n * 128 + kc * 64 + kk] * dinv
                    + bconv[kc * 64 + kk];
            }
            Xs[nl][kk] = v;
        }
        for (int i = tid; i < 4096; i += 256) {
            int kk = i >> 6, c = i & 63;
            Ws[kk][c] = Wmix[(kc * 64 + kk) * 64 + c];
        }
        __syncthreads();
#pragma unroll 8
        for (int kk = 0; kk < 64; kk++) {
            float4 b = *reinterpret_cast<float4*>(&Ws[kk][ct * 4]);
#pragma unroll
            for (int i = 0; i < 4; i++) {
                float a = Xs[rt * 4 + i][kk];
                acc[i][0] += a * b.x; acc[i][1] += a * b.y;
                acc[i][2] += a * b.z; acc[i][3] += a * b.w;
            }
        }
    }
#pragma unroll
    for (int i = 0; i < 4; i++) {
        int n = n0 + rt * 4 + i;
        if (n < NN) {
            float4 o;
            o.x = fmaxf(acc[i][0] + bmix[ct * 4 + 0], 0.f);
            o.y = fmaxf(acc[i][1] + bmix[ct * 4 + 1], 0.f);
            o.z = fmaxf(acc[i][2] + bmix[ct * 4 + 2], 0.f);
            o.w = fmaxf(acc[i][3] + bmix[ct * 4 + 3], 0.f);
            *reinterpret_cast<float4*>(&g_h[(size_t)n * 64 + ct * 4]) = o;
        }
    }
}

// ---------------- fused GRU: [h|h_prev] @ Bcomb (128x256), gate epilogue ----
__global__ void k_gru(const float* __restrict__ h_prev, float* __restrict__ out_h) {
    __shared__ float Xs[64][32];   // node-major, 32-k chunk
    __shared__ float Bs[32][256];
    int n0 = blockIdx.x * 64;
    int tid = threadIdx.x;
    int rt = tid >> 5, ct = tid & 31;   // 8 row-groups x 8 nodes; ct -> j in {2ct, 2ct+1}
    float acc[8][8] = {};               // [node][jj*4 + seg]
    for (int kc = 0; kc < 4; kc++) {
        __syncthreads();
        for (int i = tid; i < 2048; i += 256) {
            int nl = i >> 5, kk = i & 31;
            int n = n0 + nl;
            int k = kc * 32 + kk;
            float v = 0.f;
            if (n < NN)
                v = (k < 64) ? g_h[(size_t)n * 64 + k]
                             : h_prev[(size_t)n * 64 + (k - 64)];
            Xs[nl][kk] = v;
        }
        for (int i = tid; i < 8192; i += 256) {
            int kk = i >> 8, c = i & 255;
            Bs[kk][c] = g_Bcomb[(kc * 32 + kk) * 256 + c];
        }
        __syncthreads();
#pragma unroll 4
        for (int kk = 0; kk < 32; kk++) {
            float2 b0 = *reinterpret_cast<float2*>(&Bs[kk][0 * 64 + ct * 2]);
            float2 b1 = *reinterpret_cast<float2*>(&Bs[kk][1 * 64 + ct * 2]);
            float2 b2 = *reinterpret_cast<float2*>(&Bs[kk][2 * 64 + ct * 2]);
            float2 b3 = *reinterpret_cast<float2*>(&Bs[kk][3 * 64 + ct * 2]);
#pragma unroll
            for (int i = 0; i < 8; i++) {
                float a = Xs[rt * 8 + i][kk];
                acc[i][0] += a * b0.x; acc[i][4] += a * b0.y;
                acc[i][1] += a * b1.x; acc[i][5] += a * b1.y;
                acc[i][2] += a * b2.x; acc[i][6] += a * b2.y;
                acc[i][3] += a * b3.x; acc[i][7] += a * b3.y;
            }
        }
    }
#pragma unroll
    for (int i = 0; i < 8; i++) {
        int n = n0 + rt * 8 + i;
        if (n >= NN) continue;
#pragma unroll
        for (int jj = 0; jj < 2; jj++) {
            int j = ct * 2 + jj;
            float rs = acc[i][jj * 4 + 0] + g_bias[j];
            float zs = acc[i][jj * 4 + 1] + g_bias[64 + j];
            float gn = acc[i][jj * 4 + 2] + g_bias[128 + j];
            float ghn = acc[i][jj * 4 + 3] + g_bias[192 + j];
            float r = 1.f / (1.f + expf(-rs));
            float z = 1.f / (1.f + expf(-zs));
            float nv = tanhf(gn + r * ghn);
            float hp = h_prev[(size_t)n * 64 + j];
            out_h[(size_t)n * 64 + j] = (1.f - z) * nv + z * hp;
        }
    }
}

// ---------------- out = (h_next @ W_ro + b_ro)[:, :3] -----------------------
__global__ void k_out(const float* __restrict__ hn, const float* __restrict__ Wro,
                      const float* __restrict__ bro, float* __restrict__ out3) {
    __shared__ float Hs[128][65];
    int n0 = blockIdx.x * 128;
    int tid = threadIdx.x;   // 128
    for (int i = tid; i < 128 * 64; i += 128) {
        int nl = i >> 6, k = i & 63;
        int n = n0 + nl;
        Hs[nl][k] = (n < NN) ? hn[(size_t)n * 64 + k] : 0.f;
    }
    __syncthreads();
    int n = n0 + tid;
    if (n < NN) {
        float a0 = bro[0], a1 = bro[1], a2 = bro[2];
#pragma unroll 8
        for (int k = 0; k < 64; k++) {
            float h = Hs[tid][k];
            a0 += h * __ldg(&Wro[k * 64 + 0]);
            a1 += h * __ldg(&Wro[k * 64 + 1]);
            a2 += h * __ldg(&Wro[k * 64 + 2]);
        }
        out3[n * 3 + 0] = a0;
        out3[n * 3 + 1] = a1;
        out3[n * 3 + 2] = a2;
    }
}

// ---------------- launch -----------------------------------------------------
extern "C" void kernel_launch(void* const* d_in, const int* in_sizes, int n_in,
                              void* d_out, int out_size) {
    const float* x       = (const float*)d_in[0];
    const float* h_prev  = (const float*)d_in[1];
    const int* node_idx  = (const int*)d_in[2];
    const int* hedge_idx = (const int*)d_in[3];
    const int* edge_attr = (const int*)d_in[4];
    const float* W_conv  = (const float*)d_in[5];
    const float* b_conv  = (const float*)d_in[6];
    const float* W_mix   = (const float*)d_in[7];
    const float* b_mix   = (const float*)d_in[8];
    const float* W_ih    = (const float*)d_in[9];
    const float* W_hh    = (const float*)d_in[10];
    const float* b_ih    = (const float*)d_in[11];
    const float* b_hh    = (const float*)d_in[12];
    const float* W_ro    = (const float*)d_in[13];
    const float* b_ro    = (const float*)d_in[14];

    float* h_next = (float*)d_out;              // [NN*64]
    float* out3   = (float*)d_out + (size_t)NN * 64;   // [NN*3]

    k_zero<<<4096, 256>>>();
    k_prep<<<128, 256>>>(W_ih, W_hh, b_ih, b_hh);
    k_gemm_xl<<<(NN + 63) / 64, 256>>>(x, W_conv);
    k_scatterA<<<NE / 16, 256>>>(node_idx, hedge_idx, edge_attr);
    k_scale_ef<<<(NH * 32 + 255) / 256, 256>>>();
    k_scatterB<<<NE / 16, 256>>>(node_idx, hedge_idx, edge_attr);
    k_mix<<<(NN + 63) / 64, 256>>>(b_conv, W_mix, b_mix);
    k_gru<<<(NN + 63) / 64, 256>>>(h_prev, h_next);
    k_out<<<(NN + 127) / 128, 128>>>(h_next, W_ro, b_ro, out3);
}

// round 2
// speedup vs baseline: 1.1498x; 1.1498x over previous
#include <cuda_runtime.h>
#include <cstdint>

#define NN 100000
#define NH 20000
#define NE 800000

// ---------------- scratch layout: ef | no | D | B ---------------------------
#define EF_OFF 0
#define NO_OFF (NH*128)
#define D_OFF  (NH*128 + NN*128)
#define B_OFF  (NH*128 + NN*128 + 2*NN)
#define ZTOT   (NH*128 + NN*128 + 2*NN + 2*NH)

__device__ __align__(16) float g_scratch[ZTOT];
__device__ __align__(16) float g_xl[(size_t)NN*128];   // x @ [W_conv0|W_conv1]
__device__ __align__(16) float g_h[(size_t)NN*64];     // relu(mix)
// Pre-swizzled tf32 B-images: [kchunk][col][32] with perm+rotation applied
__device__ __align__(16) float g_Bxl[2*128*32];
__device__ __align__(16) float g_Bmix[4*64*32];
__device__ __align__(16) float g_Bgru[4*256*32];
__device__ float g_bias[256];    // GRU bias, seg-major
__device__ float g_bcmix[64];    // bmix + bconv @ Wmix

// ---------------- helpers ---------------------------------------------------
__device__ __forceinline__ void red_add_f4(float* addr, float4 v) {
    asm volatile("red.global.add.v4.f32 [%0], {%1,%2,%3,%4};"
                 :: "l"(addr), "f"(v.x), "f"(v.y), "f"(v.z), "f"(v.w) : "memory");
}
__device__ __forceinline__ float to_tf32(float v) {
    uint32_t u; asm("cvt.rna.tf32.f32 %0, %1;" : "=r"(u) : "f"(v));
    return __uint_as_float(u);
}
// k-pair permutation (pairs (t,t+4) adjacent) + per-row rotation, 32-col rows
__device__ __forceinline__ int swz(int kk, int row) {
    int r = kk & 7;
    int pos = (r < 4) ? (r * 2) : ((r - 4) * 2 + 1);
    int sc = (kk & 24) + pos;
    return (sc + ((row & 3) << 3)) & 31;
}
__device__ __forceinline__ void mma_tf32(float* c, const uint32_t* a,
                                         uint32_t b0, uint32_t b1) {
    asm volatile(
        "mma.sync.aligned.m16n8k8.row.col.f32.tf32.tf32.f32 "
        "{%0,%1,%2,%3}, {%4,%5,%6,%7}, {%8,%9}, {%0,%1,%2,%3};"
        : "+f"(c[0]), "+f"(c[1]), "+f"(c[2]), "+f"(c[3])
        : "r"(a[0]), "r"(a[1]), "r"(a[2]), "r"(a[3]), "r"(b0), "r"(b1));
}
__device__ __forceinline__ float sigf(float x) { return 1.f / (1.f + __expf(-x)); }
__device__ __forceinline__ float tanh_fast(float x) {
    return 1.f - 2.f / (__expf(2.f * x) + 1.f);
}

// ---------------- zero scratch ----------------------------------------------
__global__ void k_zero() {
    int i = blockIdx.x * blockDim.x + threadIdx.x;
    const int n4 = ZTOT / 4;
    float4 z = make_float4(0.f, 0.f, 0.f, 0.f);
    for (; i < n4; i += gridDim.x * blockDim.x)
        reinterpret_cast<float4*>(g_scratch)[i] = z;
}

// ---------------- prep: swizzled tf32 B-images + biases ---------------------
__global__ void k_prep(const float* __restrict__ Wc, const float* __restrict__ Wmix,
                       const float* __restrict__ bmix, const float* __restrict__ bconv,
                       const float* __restrict__ Wih, const float* __restrict__ Whh,
                       const float* __restrict__ bih, const float* __restrict__ bhh) {
    int idx = blockIdx.x * blockDim.x + threadIdx.x;
    if (idx < 8192) {                     // Bxl: [2][128][32]
        int kc = idx >> 12, rem = idx & 4095, c = rem >> 5, kk = rem & 31;
        int k = kc * 32 + kk;
        int t = c >> 6, j = c & 63;
        float v = Wc[t * 4096 + k * 64 + j];
        g_Bxl[(kc * 128 + c) * 32 + swz(kk, c)] = to_tf32(v);
    } else if (idx < 16384) {             // Bmix: [4][64][32]
        int i = idx - 8192;
        int kc = i >> 11, rem = i & 2047, c = rem >> 5, kk = rem & 31;
        int k = kc * 32 + kk;
        g_Bmix[(kc * 64 + c) * 32 + swz(kk, c)] = to_tf32(Wmix[k * 64 + c]);
    } else if (idx < 49152) {             // Bgru: [4][256][32], c = j*4+seg
        int i = idx - 16384;
        int kc = i >> 13, rem = i & 8191, c = rem >> 5, kk = rem & 31;
        int k = kc * 32 + kk;
        int j = c >> 2, seg = c & 3;
        float v = 0.f;
        if (k < 64) {
            if (seg == 0)      v = Wih[k * 192 + j];
            else if (seg == 1) v = Wih[k * 192 + 64 + j];
            else if (seg == 2) v = Wih[k * 192 + 128 + j];
        } else {
            int k2 = k - 64;
            if (seg == 0)      v = Whh[k2 * 192 + j];
            else if (seg == 1) v = Whh[k2 * 192 + 64 + j];
            else if (seg == 3) v = Whh[k2 * 192 + 128 + j];
        }
        g_Bgru[(kc * 256 + c) * 32 + swz(kk, c)] = to_tf32(v);
    } else if (idx < 49152 + 256) {       // GRU bias (seg-major)
        int c = idx - 49152;
        int seg = c >> 6, j = c & 63;
        float b;
        if (seg == 0)      b = bih[j] + bhh[j];
        else if (seg == 1) b = bih[64 + j] + bhh[64 + j];
        else if (seg == 2) b = bih[128 + j];
        else               b = bhh[128 + j];
        g_bias[c] = b;
    } else if (idx < 49152 + 256 + 64) {  // folded mix bias
        int j = idx - 49152 - 256;
        float s = bmix[j];
        for (int k = 0; k < 128; k++) s += bconv[k] * Wmix[k * 64 + j];
        g_bcmix[j] = s;
    }
}

// ---------------- GEMM 1: xl = x @ [Wc0|Wc1]   M=NN, N=128, K=64 ------------
__global__ __launch_bounds__(256) void k_mma_xl(const float* __restrict__ x) {
    __shared__ __align__(16) float As[128][32];
    __shared__ __align__(16) float Bs[128][32];
    int tid = threadIdx.x;
    int lane = tid & 31, warp = tid >> 5;
    int warpM = warp >> 1, warpN = warp & 1;
    int g = lane >> 2, t = lane & 3;
    int rot = (g & 3) << 3;
    int n0 = blockIdx.x * 128;
    float acc[2][8][4] = {};
    for (int kc = 0; kc < 2; kc++) {
        __syncthreads();
        for (int i = tid; i < 4096; i += 256) {
            int m = i >> 5, kk = i & 31;
            int n = n0 + m;
            float v = (n < NN) ? x[(size_t)n * 64 + kc * 32 + kk] : 0.f;
            As[m][swz(kk, m)] = to_tf32(v);
        }
        const float4* src = (const float4*)&g_Bxl[kc * 4096];
        float4* dst = (float4*)&Bs[0][0];
        for (int i = tid; i < 1024; i += 256) dst[i] = src[i];
        __syncthreads();
#pragma unroll
        for (int s = 0; s < 4; s++) {
            int pc = (s * 8 + 2 * t + rot) & 31;
            uint32_t a[2][4];
#pragma unroll
            for (int mt = 0; mt < 2; mt++) {
                int r = warpM * 32 + mt * 16 + g;
                float2 lo = *(const float2*)&As[r][pc];
                float2 hi = *(const float2*)&As[r + 8][pc];
                a[mt][0] = __float_as_uint(lo.x); a[mt][1] = __float_as_uint(hi.x);
                a[mt][2] = __float_as_uint(lo.y); a[mt][3] = __float_as_uint(hi.y);
            }
#pragma unroll
            for (int nt = 0; nt < 8; nt++) {
                int c = warpN * 64 + nt * 8 + g;
                float2 b = *(const float2*)&Bs[c][pc];
                uint32_t b0 = __float_as_uint(b.x), b1 = __float_as_uint(b.y);
                mma_tf32(acc[0][nt], a[0], b0, b1);
                mma_tf32(acc[1][nt], a[1], b0, b1);
            }
        }
    }
#pragma unroll
    for (int mt = 0; mt < 2; mt++) {
        int r = n0 + warpM * 32 + mt * 16 + g;
#pragma unroll
        for (int nt = 0; nt < 8; nt++) {
            int c = warpN * 64 + nt * 8 + 2 * t;
            if (r < NN)
                *(float2*)&g_xl[(size_t)r * 128 + c] =
                    make_float2(acc[mt][nt][0], acc[mt][nt][1]);
            if (r + 8 < NN)
                *(float2*)&g_xl[(size_t)(r + 8) * 128 + c] =
                    make_float2(acc[mt][nt][2], acc[mt][nt][3]);
        }
    }
}

// ---------------- scatter phase A: ef += xl[node], degrees ------------------
__global__ void k_scatterA(const int* __restrict__ ni, const int* __restrict__ hi,
                           const int* __restrict__ ea) {
    int tid = blockIdx.x * 256 + threadIdx.x;
    int e = tid >> 4, lane = tid & 15;
    if (e >= NE) return;
    int n = ni[e], h = hi[e], t = ea[e];
    float4 v = *reinterpret_cast<const float4*>(&g_xl[(size_t)n * 128 + t * 64 + lane * 4]);
    red_add_f4(&g_scratch[EF_OFF + (size_t)h * 128 + t * 64 + lane * 4], v);
    if (lane == 0) {
        atomicAdd(&g_scratch[D_OFF + t * NN + n], 1.0f);
        atomicAdd(&g_scratch[B_OFF + t * NH + h], 1.0f);
    }
}

// ---------------- ef *= Binv -------------------------------------------------
__global__ void k_scale_ef() {
    int i = blockIdx.x * 256 + threadIdx.x;
    if (i >= NH * 32) return;
    int h = i >> 5, c4 = i & 31;
    int t = c4 >> 4;
    float b = g_scratch[B_OFF + t * NH + h];
    float s = (b > 0.f) ? 1.f / b : 0.f;
    float4* p = reinterpret_cast<float4*>(&g_scratch[EF_OFF + (size_t)h * 128 + c4 * 4]);
    float4 v = *p;
    v.x *= s; v.y *= s; v.z *= s; v.w *= s;
    *p = v;
}

// ---------------- scatter phase B: no += ef[hedge] ---------------------------
__global__ void k_scatterB(const int* __restrict__ ni, const int* __restrict__ hi,
                           const int* __restrict__ ea) {
    int tid = blockIdx.x * 256 + threadIdx.x;
    int e = tid >> 4, lane = tid & 15;
    if (e >= NE) return;
    int n = ni[e], h = hi[e], t = ea[e];
    float4 v = *reinterpret_cast<const float4*>(
        &g_scratch[EF_OFF + (size_t)h * 128 + t * 64 + lane * 4]);
    red_add_f4(&g_scratch[NO_OFF + (size_t)n * 128 + t * 64 + lane * 4], v);
}

// ---------------- GEMM 2: h = relu((no*Dinv)@Wmix + bcmix)  N=64, K=128 -----
__global__ __launch_bounds__(256) void k_mma_mix() {
    __shared__ __align__(16) float As[128][32];
    __shared__ __align__(16) float Bs[64][32];
    int tid = threadIdx.x;
    int lane = tid & 31, warp = tid >> 5;
    int warpM = warp >> 1, warpN = warp & 1;
    int g = lane >> 2, t = lane & 3;
    int rot = (g & 3) << 3;
    int n0 = blockIdx.x * 128;
    float acc[2][4][4] = {};
    for (int kc = 0; kc < 4; kc++) {
        __syncthreads();
        int ty = kc >> 1;
        for (int i = tid; i < 4096; i += 256) {
            int m = i >> 5, kk = i & 31;
            int n = n0 + m;
            float v = 0.f;
            if (n < NN) {
                float d = g_scratch[D_OFF + ty * NN + n];
                float dinv = (d > 0.f) ? 1.f / d : 0.f;
                v = g_scratch[NO_OFF + (size_t)n * 128 + kc * 32 + kk] * dinv;
            }
            As[m][swz(kk, m)] = to_tf32(v);
        }
        const float4* src = (const float4*)&g_Bmix[kc * 2048];
        float4* dst = (float4*)&Bs[0][0];
        for (int i = tid; i < 512; i += 256) dst[i] = src[i];
        __syncthreads();
#pragma unroll
        for (int s = 0; s < 4; s++) {
            int pc = (s * 8 + 2 * t + rot) & 31;
            uint32_t a[2][4];
#pragma unroll
            for (int mt = 0; mt < 2; mt++) {
                int r = warpM * 32 + mt * 16 + g;
                float2 lo = *(const float2*)&As[r][pc];
                float2 hi = *(const float2*)&As[r + 8][pc];
                a[mt][0] = __float_as_uint(lo.x); a[mt][1] = __float_as_uint(hi.x);
                a[mt][2] = __float_as_uint(lo.y); a[mt][3] = __float_as_uint(hi.y);
            }
#pragma unroll
            for (int nt = 0; nt < 4; nt++) {
                int c = warpN * 32 + nt * 8 + g;
                float2 b = *(const float2*)&Bs[c][pc];
                uint32_t b0 = __float_as_uint(b.x), b1 = __float_as_uint(b.y);
                mma_tf32(acc[0][nt], a[0], b0, b1);
                mma_tf32(acc[1][nt], a[1], b0, b1);
            }
        }
    }
#pragma unroll
    for (int mt = 0; mt < 2; mt++) {
        int r = n0 + warpM * 32 + mt * 16 + g;
#pragma unroll
        for (int nt = 0; nt < 4; nt++) {
            int c = warpN * 32 + nt * 8 + 2 * t;
            float b0 = g_bcmix[c], b1 = g_bcmix[c + 1];
            if (r < NN)
                *(float2*)&g_h[(size_t)r * 64 + c] =
                    make_float2(fmaxf(acc[mt][nt][0] + b0, 0.f),
                                fmaxf(acc[mt][nt][1] + b1, 0.f));
            if (r + 8 < NN)
                *(float2*)&g_h[(size_t)(r + 8) * 64 + c] =
                    make_float2(fmaxf(acc[mt][nt][2] + b0, 0.f),
                                fmaxf(acc[mt][nt][3] + b1, 0.f));
        }
    }
}

// ---------------- GEMM 3: fused GRU  [h|h_prev]@Bgru, gate epilogue ---------
__global__ __launch_bounds__(256) void k_mma_gru(const float* __restrict__ h_prev,
                                                 float* __restrict__ out_h) {
    __shared__ __align__(16) float As[128][32];
    __shared__ __align__(16) float Bs[128][32];
    int tid = threadIdx.x;
    int lane = tid & 31, warp = tid >> 5;
    int warpM = warp >> 1, warpN = warp & 1;
    int g = lane >> 2, t = lane & 3;
    int rot = (g & 3) << 3;
    int n0 = blockIdx.x * 128;
    int cb = blockIdx.y * 128;
    float acc[2][8][4] = {};
    for (int kc = 0; kc < 4; kc++) {
        __syncthreads();
        for (int i = tid; i < 4096; i += 256) {
            int m = i >> 5, kk = i & 31;
            int n = n0 + m;
            int kg = kc * 32 + kk;
            float v = 0.f;
            if (n < NN)
                v = (kg < 64) ? g_h[(size_t)n * 64 + kg]
                              : h_prev[(size_t)n * 64 + kg - 64];
            As[m][swz(kk, m)] = to_tf32(v);
        }
        const float4* src = (const float4*)&g_Bgru[(kc * 256 + cb) * 32];
        float4* dst = (float4*)&Bs[0][0];
        for (int i = tid; i < 1024; i += 256) dst[i] = src[i];
        __syncthreads();
#pragma unroll
        for (int s = 0; s < 4; s++) {
            int pc = (s * 8 + 2 * t + rot) & 31;
            uint32_t a[2][4];
#pragma unroll
            for (int mt = 0; mt < 2; mt++) {
                int r = warpM * 32 + mt * 16 + g;
                float2 lo = *(const float2*)&As[r][pc];
                float2 hi = *(const float2*)&As[r + 8][pc];
                a[mt][0] = __float_as_uint(lo.x); a[mt][1] = __float_as_uint(hi.x);
                a[mt][2] = __float_as_uint(lo.y); a[mt][3] = __float_as_uint(hi.y);
            }
#pragma unroll
            for (int nt = 0; nt < 8; nt++) {
                int c = warpN * 64 + nt * 8 + g;
                float2 b = *(const float2*)&Bs[c][pc];
                uint32_t b0 = __float_as_uint(b.x), b1 = __float_as_uint(b.y);
                mma_tf32(acc[0][nt], a[0], b0, b1);
                mma_tf32(acc[1][nt], a[1], b0, b1);
            }
        }
    }
    // gate epilogue: cols interleaved c = j*4+seg; lane pairs exchange halves
#pragma unroll
    for (int mt = 0; mt < 2; mt++) {
#pragma unroll
        for (int nt = 0; nt < 8; nt++) {
            int cg0 = cb + warpN * 64 + nt * 8;
            int j = (cg0 >> 2) + (t >> 1);
            bool even = (t & 1) == 0;
            float br = g_bias[j], bz = g_bias[64 + j];
            float bn = g_bias[128 + j], bh = g_bias[192 + j];
#pragma unroll
            for (int rh = 0; rh < 2; rh++) {
                int n = n0 + warpM * 32 + mt * 16 + rh * 8 + g;
                float v0 = acc[mt][nt][rh * 2 + 0];
                float v1 = acc[mt][nt][rh * 2 + 1];
                float o0 = __shfl_xor_sync(0xffffffffu, v0, 1);
                float o1 = __shfl_xor_sync(0xffffffffu, v1, 1);
                if (even && n < NN) {
                    float r_ = sigf(v0 + br);
                    float z_ = sigf(v1 + bz);
                    float nv = tanh_fast((o0 + bn) + r_ * (o1 + bh));
                    float hp = h_prev[(size_t)n * 64 + j];
                    out_h[(size_t)n * 64 + j] = (1.f - z_) * nv + z_ * hp;
                }
            }
        }
    }
}

// ---------------- out = (h_next @ W_ro + b_ro)[:, :3] -----------------------
__global__ void k_out(const float* __restrict__ hn, const float* __restrict__ Wro,
                      const float* __restrict__ bro, float* __restrict__ out3) {
    __shared__ float Hs[128][65];
    int n0 = blockIdx.x * 128;
    int tid = threadIdx.x;
    for (int i = tid; i < 128 * 64; i += 128) {
        int nl = i >> 6, k = i & 63;
        int n = n0 + nl;
        Hs[nl][k] = (n < NN) ? hn[(size_t)n * 64 + k] : 0.f;
    }
    __syncthreads();
    int n = n0 + tid;
    if (n < NN) {
        float a0 = bro[0], a1 = bro[1], a2 = bro[2];
#pragma unroll 8
        for (int k = 0; k < 64; k++) {
            float h = Hs[tid][k];
            a0 += h * __ldg(&Wro[k * 64 + 0]);
            a1 += h * __ldg(&Wro[k * 64 + 1]);
            a2 += h * __ldg(&Wro[k * 64 + 2]);
        }
        out3[n * 3 + 0] = a0;
        out3[n * 3 + 1] = a1;
        out3[n * 3 + 2] = a2;
    }
}

// ---------------- launch -----------------------------------------------------
extern "C" void kernel_launch(void* const* d_in, const int* in_sizes, int n_in,
                              void* d_out, int out_size) {
    const float* x       = (const float*)d_in[0];
    const float* h_prev  = (const float*)d_in[1];
    const int* node_idx  = (const int*)d_in[2];
    const int* hedge_idx = (const int*)d_in[3];
    const int* edge_attr = (const int*)d_in[4];
    const float* W_conv  = (const float*)d_in[5];
    const float* b_conv  = (const float*)d_in[6];
    const float* W_mix   = (const float*)d_in[7];
    const float* b_mix   = (const float*)d_in[8];
    const float* W_ih    = (const float*)d_in[9];
    const float* W_hh    = (const float*)d_in[10];
    const float* b_ih    = (const float*)d_in[11];
    const float* b_hh    = (const float*)d_in[12];
    const float* W_ro    = (const float*)d_in[13];
    const float* b_ro    = (const float*)d_in[14];

    float* h_next = (float*)d_out;
    float* out3   = (float*)d_out + (size_t)NN * 64;

    k_zero<<<4096, 256>>>();
    k_prep<<<194, 256>>>(W_conv, W_mix, b_mix, b_conv, W_ih, W_hh, b_ih, b_hh);
    k_mma_xl<<<(NN + 127) / 128, 256>>>(x);
    k_scatterA<<<NE / 16, 256>>>(node_idx, hedge_idx, edge_attr);
    k_scale_ef<<<(NH * 32 + 255) / 256, 256>>>();
    k_scatterB<<<NE / 16, 256>>>(node_idx, hedge_idx, edge_attr);
    k_mma_mix<<<(NN + 127) / 128, 256>>>();
    k_mma_gru<<<dim3((NN + 127) / 128, 2), 256>>>(h_prev, h_next);
    k_out<<<(NN + 127) / 128, 128>>>(h_next, W_ro, b_ro, out3);
}